// round 9
// baseline (speedup 1.0000x reference)
#include <cuda_runtime.h>

// x: (256, 2048, 25, 2) fp32 -> 26,214,400 floats = 6,553,600 float4s.
// weights: (2048, 1) fp32; only weights[0] used.
// out[b,f,j,:] = j < 8 ? (x*c + y*s, -x*s + y*c) : (x, y), theta = weights[0].

static constexpr long long TOTAL_FLOATS = 256LL * 2048 * 25 * 2;  // 26,214,400
static constexpr int N4 = (int)(TOTAL_FLOATS / 4);                // 6,553,600
static constexpr int VPT = 4;                                     // float4s per thread
static constexpr int TPB = 256;
static constexpr int BLOCKS = N4 / (TPB * VPT);                   // 6400, exact

__global__ void __launch_bounds__(TPB, 8) rigid_rot_kernel(
    const float4* __restrict__ in,
    const float* __restrict__ w,
    float4* __restrict__ out)
{
    const int base = blockIdx.x * (TPB * VPT) + threadIdx.x;

    // Front-batched streaming loads: no reuse within or across this launch's
    // working set, so evict-first keeps both streams from thrashing L2.
    float4 v[VPT];
#pragma unroll
    for (int k = 0; k < VPT; k++)
        v[k] = __ldcs(&in[base + k * TPB]);

    float s, c;
    sincosf(__ldg(w), &s, &c);

#pragma unroll
    for (int k = 0; k < VPT; k++) {
        const int i = base + k * TPB;
        // float4 i covers joint pairs 2i and 2i+1; joint index = pair % 25.
        int j0 = (2 * i) % 25;
        int j1 = (j0 + 1 == 25) ? 0 : j0 + 1;

        // Branchless: pass-through = rotation by identity (1, 0).
        float c0 = (j0 < 8) ? c : 1.0f;
        float s0 = (j0 < 8) ? s : 0.0f;
        float c1 = (j1 < 8) ? c : 1.0f;
        float s1 = (j1 < 8) ? s : 0.0f;

        float x0 = v[k].x, y0 = v[k].y;
        float x1 = v[k].z, y1 = v[k].w;
        v[k].x = fmaf(x0, c0, y0 * s0);
        v[k].y = fmaf(-x0, s0, y0 * c0);
        v[k].z = fmaf(x1, c1, y1 * s1);
        v[k].w = fmaf(-x1, s1, y1 * c1);
    }

    // Streaming stores (evict-first): write stream must not thrash L2.
#pragma unroll
    for (int k = 0; k < VPT; k++)
        __stcs(&out[base + k * TPB], v[k]);
}

extern "C" void kernel_launch(void* const* d_in, const int* in_sizes, int n_in,
                              void* d_out, int out_size)
{
    const float4* x = (const float4*)d_in[0];
    const float*  w = (const float*)d_in[1];
    float4* out = (float4*)d_out;

    rigid_rot_kernel<<<BLOCKS, TPB>>>(x, w, out);
}